// round 13
// baseline (speedup 1.0000x reference)
#include <cuda_runtime.h>

// out[n, d] = sum_k mat[n,k] * feat[graph[n,k], d]
// N=40000, K=32, D=64. One warp per item n. Single kernel, no probe launch.
//
// Inline per-warp dtype detection (ballot of odd int32 words; int64 data has
// all-zero high words, int32 data has 16 uniform indices there).
//
// Gather: lanes split in halves; half h handles neighbor 2k+h. Each lane
// loads float4 of dims [4*sub, 4*sub+3]. K=32 processed as 2 batches of 8
// steps with an EXPLICIT load phase (8 outstanding LDG.128 per warp) before
// the FMA phase — R12 measured regs=32, i.e. ptxas kept only ~2-3 gathers in
// flight; forcing MLP=8 targets the idle L2 headroom (59% util @ 23.4us).
// shfl_xor(16) combine, half-warp float4 __stcg store (no L1 write-alloc).

#define K_NEIGH 32
#define D_LAT   64
#define BATCH   8

__global__ void __launch_bounds__(256, 3)
item_graph_sample_kernel(const float* __restrict__ feat,
                         const void* __restrict__ graph_raw,
                         const float* __restrict__ mat,
                         float* __restrict__ out,
                         int n_items)
{
    const int warp_id = (blockIdx.x * blockDim.x + threadIdx.x) >> 5;
    const int lane    = threadIdx.x & 31;
    if (warp_id >= n_items) return;

    const int half = lane >> 4;      // 0: even neighbors, 1: odd neighbors
    const int sub  = lane & 15;      // dim group: owns dims [4*sub, 4*sub+3]

    // --- inline dtype detection + index load (coalesced) ---
    const int my_i32 = ((const int*)graph_raw)[warp_id * K_NEIGH + lane];
    const unsigned nz = __ballot_sync(0xffffffffu, my_i32 != 0);
    const bool is_i64 = ((nz & 0xAAAAAAAAu) == 0u);   // all odd words zero

    long long my_idx;
    if (is_i64) {
        my_idx = ((const long long*)graph_raw)[warp_id * K_NEIGH + lane];
    } else {
        my_idx = (long long)my_i32;
    }
    const float my_w = mat[warp_id * K_NEIGH + lane];

    float4 acc = make_float4(0.0f, 0.0f, 0.0f, 0.0f);

    // 2 batches x 8 steps; each step covers two neighbor rows (one per half).
    #pragma unroll
    for (int b = 0; b < K_NEIGH / (2 * BATCH); ++b) {
        float4 v[BATCH];

        // Load phase: 8 independent LDG.128 in flight before any consumer.
        #pragma unroll
        for (int k = 0; k < BATCH; ++k) {
            const int src = 2 * (b * BATCH + k) + half;
            const long long idx = __shfl_sync(0xffffffffu, my_idx, src);
            v[k] = __ldg(reinterpret_cast<const float4*>(
                feat + idx * D_LAT + 4 * sub));
        }

        // Compute phase: weights shuffled here (no memory dependence).
        #pragma unroll
        for (int k = 0; k < BATCH; ++k) {
            const int src = 2 * (b * BATCH + k) + half;
            const float w = __shfl_sync(0xffffffffu, my_w, src);
            acc.x = fmaf(w, v[k].x, acc.x);
            acc.y = fmaf(w, v[k].y, acc.y);
            acc.z = fmaf(w, v[k].z, acc.z);
            acc.w = fmaf(w, v[k].w, acc.w);
        }
    }

    // Combine even-half (lanes 0-15) with odd-half (lanes 16-31).
    acc.x += __shfl_xor_sync(0xffffffffu, acc.x, 16);
    acc.y += __shfl_xor_sync(0xffffffffu, acc.y, 16);
    acc.z += __shfl_xor_sync(0xffffffffu, acc.z, 16);
    acc.w += __shfl_xor_sync(0xffffffffu, acc.w, 16);

    if (half == 0) {
        __stcg(reinterpret_cast<float4*>(
                   out + (long long)warp_id * D_LAT + 4 * sub), acc);
    }
}

extern "C" void kernel_launch(void* const* d_in, const int* in_sizes, int n_in,
                              void* d_out, int out_size)
{
    const float* feat  = (const float*)d_in[0];  // [N, 64] f32
    const void*  graph = d_in[1];                // [N, 32] i32 or i64
    const float* mat   = (const float*)d_in[2];  // [N, 32] f32
    float*       out   = (float*)d_out;          // [N, 64] f32

    const int n_items = in_sizes[2] / K_NEIGH;   // 40000

    const int threads = 256;                 // 8 warps = 8 items per CTA
    const int items_per_block = threads / 32;
    const int blocks = (n_items + items_per_block - 1) / items_per_block;

    item_graph_sample_kernel<<<blocks, threads>>>(feat, graph, mat, out, n_items);
}